// round 6
// baseline (speedup 1.0000x reference)
#include <cuda_runtime.h>
#include <cuda_fp16.h>
#include <math.h>

// Problem constants
#define B_SZ   64
#define BG     32            // batch-group size (u_hat slice = 67 MB, fits L2)
#define NGROUP 2
#define I_CAPS 2048
#define D_DIM  16
#define J_CAPS 32
#define K_DIM  16
#define JK     512
#define NCHUNK 32            // i-chunks (2048 / 64 i per CTA)

// Scratch (device globals — allocation-free rule)
// u_hat slice for ONE batch group: [lb][i][jk] fp16 = 67 MB (L2-resident target)
__device__ __half g_uhat[(size_t)BG * I_CAPS * JK];
__device__ float  g_part[NCHUNK * BG * JK];               // per-chunk partials
__device__ float  g_out1[B_SZ * JK];                      // squash(round1)
__device__ float  g_outc[B_SZ * JK];                      // out1 + out2

// ---- packed f32x2 helpers (FFMA2 only reachable via PTX) ------------------
__device__ __forceinline__ unsigned long long pk2(float a, float b) {
    unsigned long long r;
    asm("mov.b64 %0, {%1,%2};" : "=l"(r) : "f"(a), "f"(b));
    return r;
}
__device__ __forceinline__ void fma2(unsigned long long& d,
                                     unsigned long long a, unsigned long long b) {
    asm("fma.rn.f32x2 %0, %1, %2, %0;" : "+l"(d) : "l"(a), "l"(b));
}
__device__ __forceinline__ float2 up2(unsigned long long v) {
    float2 r;
    asm("mov.b64 {%0,%1}, %2;" : "=f"(r.x), "=f"(r.y) : "l"(v));
    return r;
}

// ---------------------------------------------------------------------------
// K1 (per group): u_hat[lb,i,j,k] = sum_d x[b0+lb,i,d] * W[i,j,d,k], fp16.
// One block (128 thr) per i. W[i] (32KB) in smem, reused across the 32 b.
// x staged pre-duplicated as (v,v): f32x2 multiplier = one LDS.64 broadcast.
// ---------------------------------------------------------------------------
__global__ void __launch_bounds__(128)
k_uhat(const float* __restrict__ x, const float* __restrict__ W, int b_base) {
    __shared__ float  Wsh[8192];
    __shared__ float2 xdup[BG][D_DIM];     // 4 KB

    const int i = blockIdx.x;
    const int t = threadIdx.x;

    {
        const float4* Wg  = reinterpret_cast<const float4*>(W + (size_t)i * 8192);
        float4*       Ws4 = reinterpret_cast<float4*>(Wsh);
        #pragma unroll
        for (int r = 0; r < 16; r++) Ws4[t + 128 * r] = Wg[t + 128 * r];
    }
    {
        #pragma unroll
        for (int r = 0; r < 4; r++) {
            const int e = t + 128 * r;        // 0..511
            const int lb = e >> 4, d = e & 15;
            const float v = x[((size_t)(b_base + lb) * I_CAPS + i) * D_DIM + d];
            xdup[lb][d] = make_float2(v, v);
        }
    }
    __syncthreads();

    const int j  = t >> 2;
    const int k0 = (t & 3) * 4;

    unsigned long long wA[D_DIM], wB[D_DIM];
    #pragma unroll
    for (int d = 0; d < D_DIM; d++) {
        const float* wp = &Wsh[j * 256 + d * 16 + k0];
        wA[d] = pk2(wp[0], wp[1]);
        wB[d] = pk2(wp[2], wp[3]);
    }

    __half* outp = g_uhat + (size_t)i * JK + 4 * t;
    #pragma unroll 2
    for (int lb = 0; lb < BG; lb++) {
        unsigned long long u01 = 0ull, u23 = 0ull;
        #pragma unroll
        for (int d = 0; d < D_DIM; d++) {
            const unsigned long long xx =
                *reinterpret_cast<const unsigned long long*>(&xdup[lb][d]);
            fma2(u01, xx, wA[d]);
            fma2(u23, xx, wB[d]);
        }
        const float2 a = up2(u01), c = up2(u23);
        __half2 h0 = __float22half2_rn(make_float2(a.x, a.y));
        __half2 h1 = __float22half2_rn(make_float2(c.x, c.y));
        uint2 st;
        st.x = *reinterpret_cast<unsigned int*>(&h0);
        st.y = *reinterpret_cast<unsigned int*>(&h1);
        *reinterpret_cast<uint2*>(outp + (size_t)lb * ((size_t)I_CAPS * JK)) = st;
    }
}

// ---------------------------------------------------------------------------
// Routing pass over the L2-resident group slice. blockIdx.y = lb (local b),
// blockIdx.x = chunk of 64 i. 4 warps x 16 i. Lane l owns j=l, all k=16
// (2x LDG.128 per i, coalesced). MODE 1: lane-local logit dot over k; softmax
// over j = 5-shuffle z-allreduce (no max subtraction; |logit| <~ 16, safe).
// Per-CTA partial -> g_part (deterministic, no atomics).
// ---------------------------------------------------------------------------
template <int MODE>
__global__ void __launch_bounds__(128, 8)
k_pass(int which_out, int b_base) {
    __shared__ float red[4][16 * 33];     // [warp][m*33 + lane], padded

    const int lb = blockIdx.y;
    const int t = threadIdx.x;
    const int w = t >> 5;
    const int l = t & 31;

    float o[16];
    if (MODE == 1) {
        const float* outv = (which_out == 0) ? g_out1 : g_outc;
        const float4* op = reinterpret_cast<const float4*>(
            outv + (size_t)(b_base + lb) * JK + l * 16);
        #pragma unroll
        for (int q = 0; q < 4; q++) {
            float4 v = op[q];
            o[q * 4] = v.x; o[q * 4 + 1] = v.y; o[q * 4 + 2] = v.z; o[q * 4 + 3] = v.w;
        }
    }

    float acc[16];
    #pragma unroll
    for (int m = 0; m < 16; m++) acc[m] = 0.f;

    const __half* base = g_uhat + ((size_t)lb * I_CAPS
                       + (size_t)(blockIdx.x * 64 + w * 16)) * JK;
    const uint4* p = reinterpret_cast<const uint4*>(base) + 2 * l;

    #pragma unroll
    for (int ii = 0; ii < 16; ii++) {
        const uint4 a0 = p[ii * 64];
        const uint4 a1 = p[ii * 64 + 1];

        float u[16];
        {
            const unsigned int* pa = &a0.x;
            const unsigned int* pb = &a1.x;
            #pragma unroll
            for (int h = 0; h < 4; h++) {
                float2 va = __half22float2(*reinterpret_cast<const __half2*>(&pa[h]));
                u[h * 2] = va.x; u[h * 2 + 1] = va.y;
                float2 vb = __half22float2(*reinterpret_cast<const __half2*>(&pb[h]));
                u[8 + h * 2] = vb.x; u[8 + h * 2 + 1] = vb.y;
            }
        }

        if (MODE == 1) {
            float lg = 0.f;
            #pragma unroll
            for (int m = 0; m < 16; m++) lg = fmaf(u[m], o[m], lg);
            const float e = __expf(lg);
            float z = e;
            z += __shfl_xor_sync(0xffffffffu, z, 1);
            z += __shfl_xor_sync(0xffffffffu, z, 2);
            z += __shfl_xor_sync(0xffffffffu, z, 4);
            z += __shfl_xor_sync(0xffffffffu, z, 8);
            z += __shfl_xor_sync(0xffffffffu, z, 16);
            const float c = __fdividef(e, z);
            #pragma unroll
            for (int m = 0; m < 16; m++) acc[m] = fmaf(c, u[m], acc[m]);
        } else {
            #pragma unroll
            for (int m = 0; m < 16; m++) acc[m] += u[m];
        }
    }

    // Cross-warp reduction: conflict-free STS, coalesced float4 STG.
    #pragma unroll
    for (int m = 0; m < 16; m++) red[w][m * 33 + l] = acc[m];
    __syncthreads();

    const int lo = t >> 2;          // source lane (j)
    const int mo = (t & 3) * 4;     // source m base (k)
    float4 s;
    float* sp = &s.x;
    #pragma unroll
    for (int c = 0; c < 4; c++) {
        float v = 0.f;
        #pragma unroll
        for (int w2 = 0; w2 < 4; w2++) v += red[w2][(mo + c) * 33 + lo];
        sp[c] = v;
    }
    *reinterpret_cast<float4*>(
        &g_part[((size_t)blockIdx.x * BG + lb) * JK + 4 * t]) = s;
}

// ---------------------------------------------------------------------------
// Squash (per group): reduce 32 chunk-partials, squash per (b,j) over k=16.
// mode 0 -> g_out1 ; mode 1 -> g_outc = g_out1 + squash ; mode 2 -> d_out.
// ---------------------------------------------------------------------------
__global__ void __launch_bounds__(512)
k_squash(int mode, float* __restrict__ dout, int b_base) {
    const int lb = blockIdx.x;
    const int t = threadIdx.x;
    const int b = b_base + lb;

    float v = 0.f;
    #pragma unroll
    for (int c = 0; c < NCHUNK; c++) v += g_part[(c * BG + lb) * JK + t];
    if (mode == 0) v *= (1.f / 32.f);

    float sq = v * v;
    sq += __shfl_xor_sync(0xffffffffu, sq, 1);
    sq += __shfl_xor_sync(0xffffffffu, sq, 2);
    sq += __shfl_xor_sync(0xffffffffu, sq, 4);
    sq += __shfl_xor_sync(0xffffffffu, sq, 8);

    const float scale = sq / ((1.f + sq) * sqrtf(sq + 1e-7f));
    const float o = scale * v;

    if (mode == 0)      g_out1[(size_t)b * JK + t] = o;
    else if (mode == 1) g_outc[(size_t)b * JK + t] = g_out1[(size_t)b * JK + t] + o;
    else                dout[(size_t)b * JK + t] = o;
}

// ---------------------------------------------------------------------------
extern "C" void kernel_launch(void* const* d_in, const int* in_sizes, int n_in,
                              void* d_out, int out_size) {
    const float* x = (const float*)d_in[0];
    const float* W = (const float*)d_in[1];
    if (n_in >= 2 && in_sizes[0] == 16777216 && in_sizes[1] == 2097152) {
        const float* tmp = x; x = W; W = tmp;
    }
    float* out = (float*)d_out;

    // Batch-grouped: each group's 67 MB u_hat slice stays L2-resident across
    // its k_uhat write and the three routing reads.
    for (int g = 0; g < NGROUP; g++) {
        const int b0 = g * BG;
        k_uhat<<<I_CAPS, 128>>>(x, W, b0);

        dim3 pg(NCHUNK, BG);
        k_pass<0><<<pg, 128>>>(0, b0);          // round 1: uniform coupling
        k_squash<<<BG, 512>>>(0, nullptr, b0);
        k_pass<1><<<pg, 128>>>(0, b0);          // round 2: logits vs out1
        k_squash<<<BG, 512>>>(1, nullptr, b0);
        k_pass<1><<<pg, 128>>>(1, b0);          // round 3: logits vs out1+out2
        k_squash<<<BG, 512>>>(2, out, b0);
    }
}

// round 9
// speedup vs baseline: 1.0149x; 1.0149x over previous
#include <cuda_runtime.h>
#include <cuda_fp16.h>
#include <math.h>

// Problem constants
#define B_SZ   64
#define BG     32            // batch-group size (u_hat slice = 67 MB)
#define NGROUP 2
#define I_CAPS 2048
#define D_DIM  16
#define J_CAPS 32
#define K_DIM  16
#define JK     512
#define NCHUNK 32            // i-chunks (2048 / 64 i per CTA)

// Scratch (device globals — allocation-free rule)
__device__ __half g_uhat[(size_t)BG * I_CAPS * JK];       // 67 MB group slice
__device__ float  g_part[NCHUNK * BG * JK];               // per-chunk partials, 2 MB
__device__ float  g_out1[B_SZ * JK];
__device__ float  g_outc[B_SZ * JK];

// ---- packed f32x2 helpers (FFMA2 only reachable via PTX) ------------------
__device__ __forceinline__ unsigned long long pk2(float a, float b) {
    unsigned long long r;
    asm("mov.b64 %0, {%1,%2};" : "=l"(r) : "f"(a), "f"(b));
    return r;
}
__device__ __forceinline__ void fma2(unsigned long long& d,
                                     unsigned long long a, unsigned long long b) {
    asm("fma.rn.f32x2 %0, %1, %2, %0;" : "+l"(d) : "l"(a), "l"(b));
}
__device__ __forceinline__ float2 up2(unsigned long long v) {
    float2 r;
    asm("mov.b64 {%0,%1}, %2;" : "=f"(r.x), "=f"(r.y) : "l"(v));
    return r;
}

// ---- L2 eviction-priority loads (32B .v4.b64 — the only form ptxas takes) --
struct U8 { uint4 a, b; };

__device__ __forceinline__ U8 ldg_v8_el(const void* p) {          // promote/keep
    U8 v;
    asm("ld.global.L2::evict_last.v4.b64 {%0,%1,%2,%3}, [%4];"
        : "=l"(*(unsigned long long*)&v.a.x),
          "=l"(*(unsigned long long*)&v.a.z),
          "=l"(*(unsigned long long*)&v.b.x),
          "=l"(*(unsigned long long*)&v.b.z) : "l"(p));
    return v;
}
__device__ __forceinline__ U8 ldg_v8_ef(const void* p) {          // dead data
    U8 v;
    asm("ld.global.L2::evict_first.v4.b64 {%0,%1,%2,%3}, [%4];"
        : "=l"(*(unsigned long long*)&v.a.x),
          "=l"(*(unsigned long long*)&v.a.z),
          "=l"(*(unsigned long long*)&v.b.x),
          "=l"(*(unsigned long long*)&v.b.z) : "l"(p));
    return v;
}
__device__ __forceinline__ U8 ldg_v8_stream(const void* p) {      // W: stream once
    U8 v;
    asm("ld.global.nc.L2::evict_first.v4.b64 {%0,%1,%2,%3}, [%4];"
        : "=l"(*(unsigned long long*)&v.a.x),
          "=l"(*(unsigned long long*)&v.a.z),
          "=l"(*(unsigned long long*)&v.b.x),
          "=l"(*(unsigned long long*)&v.b.z) : "l"(p));
    return v;
}

// ---------------------------------------------------------------------------
// K1 (per group): u_hat[lb,i,j,k] = sum_d x[b0+lb,i,d] * W[i,j,d,k], fp16.
// One block (128 thr) per i. W streamed 32B/ld with nc.evict_first so it never
// evicts the u_hat slice. u_hat stores are plain (evict_normal; ptxas rejects
// evict_last on <32B stores) — pass<0>'s evict_last READS promote the lines.
// ---------------------------------------------------------------------------
__global__ void __launch_bounds__(128)
k_uhat(const float* __restrict__ x, const float* __restrict__ W, int b_base) {
    __shared__ float  Wsh[8192];
    __shared__ float2 xdup[BG][D_DIM];

    const int i = blockIdx.x;
    const int t = threadIdx.x;

    {
        const char* Wg = reinterpret_cast<const char*>(W + (size_t)i * 8192);
        U8* Ws8 = reinterpret_cast<U8*>(Wsh);
        #pragma unroll
        for (int r = 0; r < 8; r++)
            Ws8[t + 128 * r] = ldg_v8_stream(Wg + 32 * (t + 128 * r));
    }
    {
        #pragma unroll
        for (int r = 0; r < 4; r++) {
            const int e = t + 128 * r;
            const int lb = e >> 4, d = e & 15;
            const float v = x[((size_t)(b_base + lb) * I_CAPS + i) * D_DIM + d];
            xdup[lb][d] = make_float2(v, v);
        }
    }
    __syncthreads();

    const int j  = t >> 2;
    const int k0 = (t & 3) * 4;

    unsigned long long wA[D_DIM], wB[D_DIM];
    #pragma unroll
    for (int d = 0; d < D_DIM; d++) {
        const float* wp = &Wsh[j * 256 + d * 16 + k0];
        wA[d] = pk2(wp[0], wp[1]);
        wB[d] = pk2(wp[2], wp[3]);
    }

    __half* outp = g_uhat + (size_t)i * JK + 4 * t;
    #pragma unroll 2
    for (int lb = 0; lb < BG; lb++) {
        unsigned long long u01 = 0ull, u23 = 0ull;
        #pragma unroll
        for (int d = 0; d < D_DIM; d++) {
            const unsigned long long xx =
                *reinterpret_cast<const unsigned long long*>(&xdup[lb][d]);
            fma2(u01, xx, wA[d]);
            fma2(u23, xx, wB[d]);
        }
        const float2 a = up2(u01), c = up2(u23);
        __half2 h0 = __float22half2_rn(make_float2(a.x, a.y));
        __half2 h1 = __float22half2_rn(make_float2(c.x, c.y));
        uint2 st;
        st.x = *reinterpret_cast<unsigned int*>(&h0);
        st.y = *reinterpret_cast<unsigned int*>(&h1);
        *reinterpret_cast<uint2*>(outp + (size_t)lb * ((size_t)I_CAPS * JK)) = st;
    }
}

// ---------------------------------------------------------------------------
// Routing pass over the group slice. blockIdx.y = lb, blockIdx.x = chunk of
// 64 i. Lane l owns j=l, all k=16: ONE 32B load per i (256-bit LDG).
// KEEP=1: evict_last (promote slice; more passes coming); KEEP=0 (final pass):
// evict_first (release L2 for the next group).
// MODE 1: lane-local logit dot; softmax over j = 5-shuffle z-allreduce.
// ---------------------------------------------------------------------------
template <int MODE, int KEEP>
__global__ void __launch_bounds__(128, 8)
k_pass(int which_out, int b_base) {
    __shared__ float red[4][16 * 33];

    const int lb = blockIdx.y;
    const int t = threadIdx.x;
    const int w = t >> 5;
    const int l = t & 31;

    float o[16];
    if (MODE == 1) {
        const float* outv = (which_out == 0) ? g_out1 : g_outc;
        const float4* op = reinterpret_cast<const float4*>(
            outv + (size_t)(b_base + lb) * JK + l * 16);
        #pragma unroll
        for (int q = 0; q < 4; q++) {
            float4 v = op[q];
            o[q * 4] = v.x; o[q * 4 + 1] = v.y; o[q * 4 + 2] = v.z; o[q * 4 + 3] = v.w;
        }
    }

    float acc[16];
    #pragma unroll
    for (int m = 0; m < 16; m++) acc[m] = 0.f;

    const __half* base = g_uhat + ((size_t)lb * I_CAPS
                       + (size_t)(blockIdx.x * 64 + w * 16)) * JK;
    const char* p = reinterpret_cast<const char*>(base) + 32 * l;

    #pragma unroll
    for (int ii = 0; ii < 16; ii++) {
        const U8 r8 = KEEP ? ldg_v8_el(p + ii * 1024) : ldg_v8_ef(p + ii * 1024);

        float u[16];
        {
            const unsigned int* pa = &r8.a.x;
            const unsigned int* pb = &r8.b.x;
            #pragma unroll
            for (int h = 0; h < 4; h++) {
                float2 va = __half22float2(*reinterpret_cast<const __half2*>(&pa[h]));
                u[h * 2] = va.x; u[h * 2 + 1] = va.y;
                float2 vb = __half22float2(*reinterpret_cast<const __half2*>(&pb[h]));
                u[8 + h * 2] = vb.x; u[8 + h * 2 + 1] = vb.y;
            }
        }

        if (MODE == 1) {
            float lg = 0.f;
            #pragma unroll
            for (int m = 0; m < 16; m++) lg = fmaf(u[m], o[m], lg);
            const float e = __expf(lg);
            float z = e;
            z += __shfl_xor_sync(0xffffffffu, z, 1);
            z += __shfl_xor_sync(0xffffffffu, z, 2);
            z += __shfl_xor_sync(0xffffffffu, z, 4);
            z += __shfl_xor_sync(0xffffffffu, z, 8);
            z += __shfl_xor_sync(0xffffffffu, z, 16);
            const float c = __fdividef(e, z);
            #pragma unroll
            for (int m = 0; m < 16; m++) acc[m] = fmaf(c, u[m], acc[m]);
        } else {
            #pragma unroll
            for (int m = 0; m < 16; m++) acc[m] += u[m];
        }
    }

    #pragma unroll
    for (int m = 0; m < 16; m++) red[w][m * 33 + l] = acc[m];
    __syncthreads();

    const int lo = t >> 2;
    const int mo = (t & 3) * 4;
    float4 s;
    float* sp = &s.x;
    #pragma unroll
    for (int c = 0; c < 4; c++) {
        float v = 0.f;
        #pragma unroll
        for (int w2 = 0; w2 < 4; w2++) v += red[w2][(mo + c) * 33 + lo];
        sp[c] = v;
    }
    *reinterpret_cast<float4*>(
        &g_part[((size_t)blockIdx.x * BG + lb) * JK + 4 * t]) = s;
}

// ---------------------------------------------------------------------------
// Squash (per group).
// ---------------------------------------------------------------------------
__global__ void __launch_bounds__(512)
k_squash(int mode, float* __restrict__ dout, int b_base) {
    const int lb = blockIdx.x;
    const int t = threadIdx.x;
    const int b = b_base + lb;

    float v = 0.f;
    #pragma unroll
    for (int c = 0; c < NCHUNK; c++) v += g_part[(c * BG + lb) * JK + t];
    if (mode == 0) v *= (1.f / 32.f);

    float sq = v * v;
    sq += __shfl_xor_sync(0xffffffffu, sq, 1);
    sq += __shfl_xor_sync(0xffffffffu, sq, 2);
    sq += __shfl_xor_sync(0xffffffffu, sq, 4);
    sq += __shfl_xor_sync(0xffffffffu, sq, 8);

    const float scale = sq / ((1.f + sq) * sqrtf(sq + 1e-7f));
    const float o = scale * v;

    if (mode == 0)      g_out1[(size_t)b * JK + t] = o;
    else if (mode == 1) g_outc[(size_t)b * JK + t] = g_out1[(size_t)b * JK + t] + o;
    else                dout[(size_t)b * JK + t] = o;
}

// ---------------------------------------------------------------------------
extern "C" void kernel_launch(void* const* d_in, const int* in_sizes, int n_in,
                              void* d_out, int out_size) {
    const float* x = (const float*)d_in[0];
    const float* W = (const float*)d_in[1];
    if (n_in >= 2 && in_sizes[0] == 16777216 && in_sizes[1] == 2097152) {
        const float* tmp = x; x = W; W = tmp;
    }
    float* out = (float*)d_out;

    for (int g = 0; g < NGROUP; g++) {
        const int b0 = g * BG;
        k_uhat<<<I_CAPS, 128>>>(x, W, b0);

        dim3 pg(NCHUNK, BG);
        k_pass<0, 1><<<pg, 128>>>(0, b0);        // round 1 (promote slice)
        k_squash<<<BG, 512>>>(0, nullptr, b0);
        k_pass<1, 1><<<pg, 128>>>(0, b0);        // round 2 (keep slice)
        k_squash<<<BG, 512>>>(1, nullptr, b0);
        k_pass<1, 0><<<pg, 128>>>(1, b0);        // round 3 (release slice)
        k_squash<<<BG, 512>>>(2, out, b0);
    }
}